// round 1
// baseline (speedup 1.0000x reference)
#include <cuda_runtime.h>

// Path_Embedding: fused gather + conv1d(k=2) + time-maxpool + cross-row maxpool.
//
// Math: out[b][c] = bias[c] + max over a in [0,16), w in [0,4) of
//         sum_j e[a][w][j]*W0[c][j] + e[a][w+1][j]*W1[c][j]
// where e[a][t] = tables[path_type[t]][ path_input[a*512 + b/16, b%16, t] ]
//
// One block per output row b (8192 blocks, 256 threads).
// f32x2 packed FMA along the reduction axis j: e-pairs and w-pairs are both
// naturally contiguous -> LDS.128 gives two 64-bit packed operands, no MOVs.

typedef unsigned long long u64;

#define VOCAB 100000
#define TT 5
#define PP 16
#define DD 64
#define AA 16
#define WPAD 68   // 68*4B = 272B row stride: 16B-aligned, 4-lane-group bank spread

__device__ __forceinline__ void ffma2(u64 &d, u64 a, u64 b) {
    asm("fma.rn.f32x2 %0, %1, %2, %0;" : "+l"(d) : "l"(a), "l"(b));
}

__global__ __launch_bounds__(256) void path_emb_kernel(
    const int*   __restrict__ path_input,   // [8192,16,5] int32
    const int*   __restrict__ path_type,    // [5] int32
    const float* __restrict__ tables,       // [3,100000,64] f32
    const float* __restrict__ conv_w,       // [64,64,2] f32
    const float* __restrict__ conv_b,       // [64] f32
    float*       __restrict__ out)          // [8192,64] f32
{
    extern __shared__ char smem_raw[];
    // layout: e_s 20480B | w0s 17408B | w1s 17408B | red 1024B | idx 320B
    float (*e_s)[TT][DD] = reinterpret_cast<float(*)[TT][DD]>(smem_raw);
    float (*w0s)[WPAD]   = reinterpret_cast<float(*)[WPAD]>(smem_raw + 20480);
    float (*w1s)[WPAD]   = reinterpret_cast<float(*)[WPAD]>(smem_raw + 20480 + 17408);
    float (*red)[DD]     = reinterpret_cast<float(*)[DD]>(smem_raw + 55296);
    int   (*idx_s)[TT]   = reinterpret_cast<int(*)[TT]>(smem_raw + 56320);

    const int tid = threadIdx.x;
    const int b   = blockIdx.x;
    const int p   = b & 15;
    const int nb  = b >> 4;

    // ---- stage 0: flat table-row indices for the 16x5 embedding rows ----
    if (tid < AA * TT) {
        int a = tid / TT, t = tid - a * TT;
        int n_idx = a * 512 + nb;                       // a*512 + b/16
        int raw = path_input[(n_idx * PP + p) * TT + t];
        idx_s[a][t] = path_type[t] * VOCAB + raw;       // flat row in [3*VOCAB, 64]
    }
    // ---- stage 0b: stage conv weights, de-interleaved, j-contiguous per o ----
    const float2* cw2 = reinterpret_cast<const float2*>(conv_w);
    #pragma unroll
    for (int it = 0; it < 16; it++) {
        int i = tid + it * 256;            // i = o*64 + j, i < 4096
        int o = i >> 6, j = i & 63;
        float2 wv = cw2[i];                // (W0[o][j], W1[o][j])
        w0s[o][j] = wv.x;
        w1s[o][j] = wv.y;
    }
    __syncthreads();

    // ---- stage 1: gather 80 embedding rows (16 a x 5 t x 64 f32), float4 ----
    const float4* tab4 = reinterpret_cast<const float4*>(tables);
    #pragma unroll
    for (int it = 0; it < 5; it++) {
        int k = tid + it * 256;            // 1280 = 80 rows * 16 float4
        int row = k >> 4;                  // 0..79
        int q = k & 15;
        int a = row / TT, t = row - a * TT;
        float4 v = __ldg(&tab4[(long long)idx_s[a][t] * 16 + q]);
        *reinterpret_cast<float4*>(&e_s[a][t][q * 4]) = v;
    }
    __syncthreads();

    // ---- stage 2: conv + window-max, f32x2 packed along j ----
    const int o   = tid & 63;              // output channel
    const int grp = tid >> 6;              // 0..3, owns a = grp*4 .. grp*4+3

    u64 s[4][4];                           // [ai][w] packed partial sums over j
    #pragma unroll
    for (int ai = 0; ai < 4; ai++)
        #pragma unroll
        for (int w = 0; w < 4; w++) s[ai][w] = 0ull;   // (0.f, 0.f)

    const ulonglong2* w0p = reinterpret_cast<const ulonglong2*>(w0s[o]);
    const ulonglong2* w1p = reinterpret_cast<const ulonglong2*>(w1s[o]);

    #pragma unroll 4
    for (int jj = 0; jj < 16; jj++) {      // j = 4*jj
        ulonglong2 w0v = w0p[jj];          // (W0[j],W0[j+1]) , (W0[j+2],W0[j+3])
        ulonglong2 w1v = w1p[jj];
        #pragma unroll
        for (int ai = 0; ai < 4; ai++) {
            const int a = (grp << 2) + ai;
            ulonglong2 ev[5];
            #pragma unroll
            for (int t = 0; t < 5; t++)    // broadcast LDS.128 per (a,t)
                ev[t] = *reinterpret_cast<const ulonglong2*>(&e_s[a][t][jj << 2]);
            #pragma unroll
            for (int w = 0; w < 4; w++) {
                ffma2(s[ai][w], ev[w].x,     w0v.x);
                ffma2(s[ai][w], ev[w].y,     w0v.y);
                ffma2(s[ai][w], ev[w + 1].x, w1v.x);
                ffma2(s[ai][w], ev[w + 1].y, w1v.y);
            }
        }
    }

    // horizontal add of the two j-lanes, max over windows, max over this
    // thread's 4 a-rows
    float m = -3.402823466e38f;
    #pragma unroll
    for (int ai = 0; ai < 4; ai++) {
        #pragma unroll
        for (int w = 0; w < 4; w++) {
            u64 sv = s[ai][w];
            float lo = __uint_as_float((unsigned)sv);
            float hi = __uint_as_float((unsigned)(sv >> 32));
            m = fmaxf(m, lo + hi);
        }
    }
    red[grp][o] = m;
    __syncthreads();

    // ---- stage 3: max over the 4 groups (= all 16 a), add bias, store ----
    if (tid < 64) {
        float r = fmaxf(fmaxf(red[0][tid], red[1][tid]),
                        fmaxf(red[2][tid], red[3][tid]));
        out[(long long)b * 64 + tid] = r + conv_b[tid];
    }
}

extern "C" void kernel_launch(void* const* d_in, const int* in_sizes, int n_in,
                              void* d_out, int out_size) {
    const int*   path_input = (const int*)d_in[0];
    const int*   path_type  = (const int*)d_in[1];
    const float* tables     = (const float*)d_in[2];
    const float* conv_w     = (const float*)d_in[3];
    const float* conv_b     = (const float*)d_in[4];
    float* out = (float*)d_out;

    // >48KB smem needs the opt-in attribute; host-side, not a stream op,
    // safe (and idempotent) under graph capture.
    cudaFuncSetAttribute(path_emb_kernel,
                         cudaFuncAttributeMaxDynamicSharedMemorySize, 57344);

    path_emb_kernel<<<8192, 256, 56640>>>(path_input, path_type, tables,
                                          conv_w, conv_b, out);
}